// round 2
// baseline (speedup 1.0000x reference)
#include <cuda_runtime.h>
#include <cuda_bf16.h>
#include <mma.h>
#include <stdint.h>

using namespace nvcuda;

#define NR   8192
#define DD   1024
#define BM   128
#define NBLK 64            // NR / BM
#define BK   32
#define NKT  (DD / BK)     // 32 k-tiles
#define LDA  40            // smem leading dim for bf16 tiles (pad 32 -> 40)
#define LDLOG 132          // smem leading dim for f32 logits tile
#define INV_T 14.285714285714286f
#define C1    20.609929155556602f   /* (1/0.07) * log2(e) */

// dynamic smem: union of staging (2*2*128*40*2 = 40960B) and logits tile
// logits: 128*132*4 = 67584B, then col partials 8*128*4 = 4096B
#define SMEM_LOG_BYTES   67584
#define SMEM_TOTAL_BYTES 71680

// ------------- device scratch (static allocations only) -------------
__device__ __align__(256) __nv_bfloat16 g_qn[NR * DD];
__device__ __align__(256) __nv_bfloat16 g_kn[NR * DD];
__device__ float g_row_part[NBLK * NR];   // [col-block j][global row]
__device__ float g_col_part[NBLK * NR];   // [row-block i][global col]
__device__ float g_diag[NR];
__device__ float g_block_part[32];

// ------------- fast exp2 on the FMA pipe (no MUFU) -------------
// valid for y in ~[-120, 1]; here y in [-42, ~0.01]
__device__ __forceinline__ float exp2_fast(float y) {
    float t = y + 12582912.0f;                       // 1.5 * 2^23 magic
    int   n = __float_as_int(t) - __float_as_int(12582912.0f);
    float f = y - (t - 12582912.0f);                 // f in [-0.5, 0.5]
    float p = 1.3333558146e-3f;                      // Taylor of 2^f
    p = fmaf(p, f, 9.6181291076e-3f);
    p = fmaf(p, f, 5.5504108664e-2f);
    p = fmaf(p, f, 2.4022650696e-1f);
    p = fmaf(p, f, 6.9314718056e-1f);
    p = fmaf(p, f, 1.0f);
    return __int_as_float(__float_as_int(p) + (n << 23));  // * 2^n (result stays normal)
}

// ------------- kernel 1: L2-normalize rows, write bf16 -------------
__global__ void norm_kernel(const float* __restrict__ q, const float* __restrict__ k) {
    int row = blockIdx.x;
    const float* src = blockIdx.y ? k : q;
    __nv_bfloat16* dst = blockIdx.y ? g_kn : g_qn;
    int tid = threadIdx.x;

    float4 v = reinterpret_cast<const float4*>(src + (size_t)row * DD)[tid];
    float s = v.x * v.x + v.y * v.y + v.z * v.z + v.w * v.w;
    #pragma unroll
    for (int o = 16; o; o >>= 1) s += __shfl_xor_sync(0xffffffffu, s, o);

    __shared__ float red[8];
    __shared__ float inv_s;
    int w = tid >> 5, l = tid & 31;
    if (l == 0) red[w] = s;
    __syncthreads();
    if (tid == 0) {
        float t = 0.f;
        #pragma unroll
        for (int i = 0; i < 8; i++) t += red[i];
        inv_s = 1.0f / fmaxf(sqrtf(t), 1e-12f);
    }
    __syncthreads();
    float inv = inv_s;

    __nv_bfloat162 p0, p1;
    p0.x = __float2bfloat16(v.x * inv);
    p0.y = __float2bfloat16(v.y * inv);
    p1.x = __float2bfloat16(v.z * inv);
    p1.y = __float2bfloat16(v.w * inv);
    __nv_bfloat162* d2 = reinterpret_cast<__nv_bfloat162*>(dst + (size_t)row * DD);
    d2[tid * 2]     = p0;
    d2[tid * 2 + 1] = p1;
}

// ------------- kernel 2: fused 128x128 logits tile: GEMM + exp + tile reductions -------------
extern __shared__ char smem_raw[];

__global__ void __launch_bounds__(256) gemm_tile_kernel() {
    const int bi = blockIdx.y;   // row block (query)
    const int bj = blockIdx.x;   // col block (key)
    const int tid = threadIdx.x;

    __nv_bfloat16* As = reinterpret_cast<__nv_bfloat16*>(smem_raw);           // [2][128][LDA]
    __nv_bfloat16* Bs = As + 2 * BM * LDA;
    float* LOG  = reinterpret_cast<float*>(smem_raw);                          // union with staging
    float* COLP = reinterpret_cast<float*>(smem_raw + SMEM_LOG_BYTES);         // [8][128]

    // staging load mapping: 2 threads per row, 32B (2x uint4) each
    const int r = tid >> 1, h = tid & 1;
    const uint4* gq = reinterpret_cast<const uint4*>(g_qn) + (size_t)(bi * BM + r) * (DD / 8);
    const uint4* gk = reinterpret_cast<const uint4*>(g_kn) + (size_t)(bj * BM + r) * (DD / 8);
    uint4* sa = reinterpret_cast<uint4*>(As);   // stage stride = 128*LDA/8 = 640
    uint4* sb = reinterpret_cast<uint4*>(Bs);
    const int sidx = r * (LDA / 8) + h * 2;     // LDA/8 = 5

    wmma::fragment<wmma::accumulator, 16, 16, 16, float> acc[2][4];
    #pragma unroll
    for (int fr = 0; fr < 2; fr++)
        #pragma unroll
        for (int fc = 0; fc < 4; fc++) wmma::fill_fragment(acc[fr][fc], 0.0f);

    const int wid = tid >> 5;
    const int wr = wid >> 1;   // 0..3: 32-row strip
    const int wc = wid & 1;    // 0..1: 64-col strip

    // preload stage 0
    {
        int gi = h * 2;
        uint4 a0 = gq[gi], a1 = gq[gi + 1];
        uint4 b0 = gk[gi], b1 = gk[gi + 1];
        sa[sidx] = a0; sa[sidx + 1] = a1;
        sb[sidx] = b0; sb[sidx + 1] = b1;
    }
    __syncthreads();

    for (int kt = 0; kt < NKT; ++kt) {
        uint4 a0, a1, b0, b1;
        const bool pre = (kt + 1) < NKT;
        if (pre) {
            int gi = (kt + 1) * 4 + h * 2;
            a0 = gq[gi]; a1 = gq[gi + 1];
            b0 = gk[gi]; b1 = gk[gi + 1];
        }
        const __nv_bfloat16* at = As + (kt & 1) * BM * LDA;
        const __nv_bfloat16* bt = Bs + (kt & 1) * BM * LDA;

        #pragma unroll
        for (int ks = 0; ks < 2; ++ks) {
            wmma::fragment<wmma::matrix_a, 16, 16, 16, __nv_bfloat16, wmma::row_major> af[2];
            wmma::fragment<wmma::matrix_b, 16, 16, 16, __nv_bfloat16, wmma::col_major> bf[4];
            #pragma unroll
            for (int fr = 0; fr < 2; fr++)
                wmma::load_matrix_sync(af[fr], at + (wr * 32 + fr * 16) * LDA + ks * 16, LDA);
            #pragma unroll
            for (int fc = 0; fc < 4; fc++)
                wmma::load_matrix_sync(bf[fc], bt + (wc * 64 + fc * 16) * LDA + ks * 16, LDA);
            #pragma unroll
            for (int fr = 0; fr < 2; fr++)
                #pragma unroll
                for (int fc = 0; fc < 4; fc++)
                    wmma::mma_sync(acc[fr][fc], af[fr], bf[fc], acc[fr][fc]);
        }

        if (pre) {
            int so = ((kt + 1) & 1) * 640;
            sa[so + sidx] = a0; sa[so + sidx + 1] = a1;
            sb[so + sidx] = b0; sb[so + sidx + 1] = b1;
        }
        __syncthreads();
    }

    // dump raw dots (already synced: staging no longer needed)
    #pragma unroll
    for (int fr = 0; fr < 2; fr++)
        #pragma unroll
        for (int fc = 0; fc < 4; fc++)
            wmma::store_matrix_sync(LOG + (wr * 32 + fr * 16) * LDLOG + wc * 64 + fc * 16,
                                    acc[fr][fc], LDLOG, wmma::mem_row_major);
    __syncthreads();

    if (bi == bj && tid < BM)
        g_diag[bi * BM + tid] = LOG[tid * LDLOG + tid] * INV_T;

    // epilogue: e = exp((dot - 1)/T); row sums via warp shuffle, col sums in registers
    const int lane = tid & 31, w = tid >> 5;
    float ca0 = 0.f, ca1 = 0.f, ca2 = 0.f, ca3 = 0.f;
    #pragma unroll
    for (int it = 0; it < 16; ++it) {
        int row = w + it * 8;
        float4 v = *reinterpret_cast<const float4*>(LOG + row * LDLOG + lane * 4);
        float e0 = exp2_fast((v.x - 1.0f) * C1);
        float e1 = exp2_fast((v.y - 1.0f) * C1);
        float e2 = exp2_fast((v.z - 1.0f) * C1);
        float e3 = exp2_fast((v.w - 1.0f) * C1);
        ca0 += e0; ca1 += e1; ca2 += e2; ca3 += e3;
        float rs = (e0 + e1) + (e2 + e3);
        #pragma unroll
        for (int o = 16; o; o >>= 1) rs += __shfl_xor_sync(0xffffffffu, rs, o);
        if (lane == 0) g_row_part[(size_t)bj * NR + bi * BM + row] = rs;
    }
    COLP[w * 128 + lane * 4 + 0] = ca0;
    COLP[w * 128 + lane * 4 + 1] = ca1;
    COLP[w * 128 + lane * 4 + 2] = ca2;
    COLP[w * 128 + lane * 4 + 3] = ca3;
    __syncthreads();
    if (tid < BM) {
        float cs = 0.f;
        #pragma unroll
        for (int w2 = 0; w2 < 8; ++w2) cs += COLP[w2 * 128 + tid];
        g_col_part[(size_t)bi * NR + bj * BM + tid] = cs;
    }
}

// ------------- kernel 3: per-row lse combine + block partial sums -------------
__global__ void reduce_rows_kernel() {
    int r = blockIdx.x * 256 + threadIdx.x;
    float rs = 0.f, cs = 0.f;
    #pragma unroll 8
    for (int j = 0; j < NBLK; j++) {
        rs += g_row_part[(size_t)j * NR + r];
        cs += g_col_part[(size_t)j * NR + r];
    }
    // lse_row = log(rs) + 1/T ; contribution = 0.5*(lse_row + lse_col) - diag
    float c = 0.5f * (logf(rs) + logf(cs)) + INV_T - g_diag[r];

    #pragma unroll
    for (int o = 16; o; o >>= 1) c += __shfl_xor_sync(0xffffffffu, c, o);
    __shared__ float red[8];
    int w = threadIdx.x >> 5, l = threadIdx.x & 31;
    if (l == 0) red[w] = c;
    __syncthreads();
    if (threadIdx.x == 0) {
        float t = 0.f;
        #pragma unroll
        for (int i = 0; i < 8; i++) t += red[i];
        g_block_part[blockIdx.x] = t;
    }
}

// ------------- kernel 4: final scalar -------------
__global__ void final_kernel(float* __restrict__ out) {
    float v = g_block_part[threadIdx.x];   // 32 threads
    #pragma unroll
    for (int o = 16; o; o >>= 1) v += __shfl_xor_sync(0xffffffffu, v, o);
    if (threadIdx.x == 0) out[0] = v * (1.0f / (float)NR);
}

// ------------- launch -------------
extern "C" void kernel_launch(void* const* d_in, const int* in_sizes, int n_in,
                              void* d_out, int out_size) {
    const float* q = (const float*)d_in[0];
    const float* k = (const float*)d_in[1];
    float* out = (float*)d_out;

    cudaFuncSetAttribute(gemm_tile_kernel,
                         cudaFuncAttributeMaxDynamicSharedMemorySize, SMEM_TOTAL_BYTES);

    norm_kernel<<<dim3(NR, 2), 256>>>(q, k);
    gemm_tile_kernel<<<dim3(NBLK, NBLK), 256, SMEM_TOTAL_BYTES>>>();
    reduce_rows_kernel<<<32, 256>>>();
    final_kernel<<<1, 32>>>(out);
}

// round 4
// speedup vs baseline: 1.4313x; 1.4313x over previous
#include <cuda_runtime.h>
#include <cuda_bf16.h>
#include <stdint.h>

// ---------------- constants ----------------
#define NR   8192
#define DD   1024
#define TM   128           // tile rows (Q block)
#define TN   256           // tile cols (K block)
#define NBI  (NR / TM)     // 64 row blocks
#define NBJ  (NR / TN)     // 32 col blocks
#define KCH  64            // bf16 per k-chunk = 128B = SW128 atom row
#define NITER (DD / KCH)   // 16
#define NSTAGE 3
#define A_BYTES (TM * 128)             // 16384
#define B_BYTES (TN * 128)             // 32768
#define STAGE_BYTES (A_BYTES + B_BYTES)
#define SMEM_TOTAL (NSTAGE * STAGE_BYTES)   // 147456

#define INV_T 14.285714285714286f
#define C1    20.609929155556602f      /* (1/0.07) * log2(e) */

// ---------------- device scratch (static only) ----------------
__device__ __align__(256) __nv_bfloat16 g_qn[NR * DD];
__device__ __align__(256) __nv_bfloat16 g_kn[NR * DD];
__device__ float g_row_part[NBJ * NR];   // [col-block j][global row]
__device__ float g_col_part[NBI * NR];   // [row-block i][global col]
__device__ float g_diag[NR];
__device__ float g_block_part[32];

// ---------------- helpers ----------------
__device__ __forceinline__ uint32_t smem_u32(const void* p) {
    uint32_t a;
    asm("{ .reg .u64 t; cvta.to.shared.u64 t, %1; cvt.u32.u64 %0, t; }" : "=r"(a) : "l"(p));
    return a;
}

__device__ __forceinline__ void cp16(uint32_t dst, const void* src) {
    asm volatile("cp.async.cg.shared.global [%0], [%1], 16;" :: "r"(dst), "l"(src) : "memory");
}

__device__ __forceinline__ void ldsm4(uint32_t (&r)[4], uint32_t addr) {
    asm volatile("ldmatrix.sync.aligned.m8n8.x4.shared.b16 {%0,%1,%2,%3}, [%4];"
                 : "=r"(r[0]), "=r"(r[1]), "=r"(r[2]), "=r"(r[3]) : "r"(addr));
}

__device__ __forceinline__ void mma16816(float (&c)[4], const uint32_t (&a)[4],
                                         uint32_t b0, uint32_t b1) {
    asm volatile(
        "mma.sync.aligned.m16n8k16.row.col.f32.bf16.bf16.f32 "
        "{%0,%1,%2,%3}, {%4,%5,%6,%7}, {%8,%9}, {%0,%1,%2,%3};"
        : "+f"(c[0]), "+f"(c[1]), "+f"(c[2]), "+f"(c[3])
        : "r"(a[0]), "r"(a[1]), "r"(a[2]), "r"(a[3]), "r"(b0), "r"(b1));
}

// fast exp2 on the FMA pipe (no MUFU); y in [-42, ~0.3] here
__device__ __forceinline__ float exp2_fast(float y) {
    float t = y + 12582912.0f;                       // 1.5 * 2^23
    int   n = __float_as_int(t) - __float_as_int(12582912.0f);
    float f = y - (t - 12582912.0f);                 // [-0.5, 0.5]
    float p = 1.3333558146e-3f;
    p = fmaf(p, f, 9.6181291076e-3f);
    p = fmaf(p, f, 5.5504108664e-2f);
    p = fmaf(p, f, 2.4022650696e-1f);
    p = fmaf(p, f, 6.9314718056e-1f);
    p = fmaf(p, f, 1.0f);
    return __int_as_float(__float_as_int(p) + (n << 23));
}

// ---------------- kernel 1: L2-normalize rows -> bf16 ----------------
__global__ void norm_kernel(const float* __restrict__ q, const float* __restrict__ k) {
    int row = blockIdx.x;
    const float* src = blockIdx.y ? k : q;
    __nv_bfloat16* dst = blockIdx.y ? g_kn : g_qn;
    int tid = threadIdx.x;

    float4 v = reinterpret_cast<const float4*>(src + (size_t)row * DD)[tid];
    float s = v.x * v.x + v.y * v.y + v.z * v.z + v.w * v.w;
    #pragma unroll
    for (int o = 16; o; o >>= 1) s += __shfl_xor_sync(0xffffffffu, s, o);

    __shared__ float red[8];
    __shared__ float inv_s;
    int w = tid >> 5, l = tid & 31;
    if (l == 0) red[w] = s;
    __syncthreads();
    if (tid == 0) {
        float t = 0.f;
        #pragma unroll
        for (int i = 0; i < 8; i++) t += red[i];
        inv_s = 1.0f / fmaxf(sqrtf(t), 1e-12f);
    }
    __syncthreads();
    float inv = inv_s;

    __nv_bfloat162 p0, p1;
    p0.x = __float2bfloat16(v.x * inv);
    p0.y = __float2bfloat16(v.y * inv);
    p1.x = __float2bfloat16(v.z * inv);
    p1.y = __float2bfloat16(v.w * inv);
    __nv_bfloat162* d2 = reinterpret_cast<__nv_bfloat162*>(dst + (size_t)row * DD);
    d2[tid * 2]     = p0;
    d2[tid * 2 + 1] = p1;
}

// ---------------- kernel 2: fused mma.sync tile ----------------
extern __shared__ char sm_raw[];

__device__ __forceinline__ void load_chunk(uint32_t sbase, int chunk, int stage,
                                           int bi, int bj, int tid) {
    uint32_t bufA = sbase + stage * STAGE_BYTES;
    uint32_t bufB = bufA + A_BYTES;
    const char* gA = (const char*)g_qn + (size_t)(bi * TM) * (DD * 2) + chunk * 128;
    const char* gB = (const char*)g_kn + (size_t)(bj * TN) * (DD * 2) + chunk * 128;
    #pragma unroll
    for (int u = 0; u < 4; u++) {            // A: 1024 x 16B
        int idx = tid + u * 256;
        int row = idx >> 3, seg = idx & 7;
        cp16(bufA + row * 128 + ((seg ^ (row & 7)) << 4),
             gA + (size_t)row * (DD * 2) + seg * 16);
    }
    #pragma unroll
    for (int u = 0; u < 8; u++) {            // B: 2048 x 16B
        int idx = tid + u * 256;
        int row = idx >> 3, seg = idx & 7;
        cp16(bufB + row * 128 + ((seg ^ (row & 7)) << 4),
             gB + (size_t)row * (DD * 2) + seg * 16);
    }
}

__global__ void __launch_bounds__(256, 1) gemm_tile_kernel() {
    const int tid = threadIdx.x;
    const int bi = blockIdx.y;     // Q block: rows bi*128..+127
    const int bj = blockIdx.x;     // K block: cols bj*256..+255
    const uint32_t sbase = smem_u32(sm_raw);

    const int wid  = tid >> 5, lane = tid & 31;
    const int mw   = wid >> 2;     // 0..1
    const int nw   = wid & 3;      // 0..3

    float acc[4][8][4];
    #pragma unroll
    for (int mf = 0; mf < 4; mf++)
        #pragma unroll
        for (int nf = 0; nf < 8; nf++)
            #pragma unroll
            for (int e = 0; e < 4; e++) acc[mf][nf][e] = 0.f;

    // prologue: stages 0,1
    #pragma unroll
    for (int c = 0; c < NSTAGE - 1; c++) {
        load_chunk(sbase, c, c, bi, bj, tid);
        asm volatile("cp.async.commit_group;" ::: "memory");
    }

    // ldmatrix lane address pieces
    const int lrow = lane & 15;        // row within 16-row frag
    const int lhalf = lane >> 4;       // 16B half within k16

    for (int c = 0; c < NITER; c++) {
        if (c < NITER - 1)
            asm volatile("cp.async.wait_group 1;" ::: "memory");
        else
            asm volatile("cp.async.wait_group 0;" ::: "memory");
        __syncthreads();

        if (c + NSTAGE - 1 < NITER) {
            load_chunk(sbase, c + NSTAGE - 1, (c + NSTAGE - 1) % NSTAGE, bi, bj, tid);
            asm volatile("cp.async.commit_group;" ::: "memory");
        }

        const uint32_t sA = sbase + (c % NSTAGE) * STAGE_BYTES;
        const uint32_t sB = sA + A_BYTES;

        #pragma unroll
        for (int kk = 0; kk < 4; kk++) {                   // 4 x k16
            const int seg = (kk << 1) | lhalf;             // 16B seg 0..7
            uint32_t a[4][4], b[4][4];
            #pragma unroll
            for (int mf = 0; mf < 4; mf++) {
                int row = mw * 64 + mf * 16 + lrow;
                ldsm4(a[mf], sA + row * 128 + (((seg) ^ (row & 7)) << 4));
            }
            #pragma unroll
            for (int nf = 0; nf < 4; nf++) {
                int row = nw * 64 + nf * 16 + lrow;
                ldsm4(b[nf], sB + row * 128 + (((seg) ^ (row & 7)) << 4));
            }
            #pragma unroll
            for (int mf = 0; mf < 4; mf++)
                #pragma unroll
                for (int nf = 0; nf < 4; nf++) {
                    mma16816(acc[mf][nf * 2 + 0], a[mf], b[nf][0], b[nf][2]);
                    mma16816(acc[mf][nf * 2 + 1], a[mf], b[nf][1], b[nf][3]);
                }
        }
    }
    __syncthreads();   // stage smem now free for epilogue reuse

    // ---- epilogue: diag, exp, row/col partial sums ----
    float* rowp = reinterpret_cast<float*>(sm_raw);          // [4][128]
    float* colp = reinterpret_cast<float*>(sm_raw) + 512;    // [2][256]

    const bool hd = (bj == (bi >> 1));
    const int r0 = bi * TM + mw * 64 + (lane >> 2);          // + mf*16 (+8)
    const int c0 = bj * TN + nw * 64 + 2 * (lane & 3);       // + nfq*8 (+1)

    float rs[4][2];
    float cs[8][2];
    #pragma unroll
    for (int mf = 0; mf < 4; mf++) { rs[mf][0] = 0.f; rs[mf][1] = 0.f; }
    #pragma unroll
    for (int nf = 0; nf < 8; nf++) { cs[nf][0] = 0.f; cs[nf][1] = 0.f; }

    #pragma unroll
    for (int mf = 0; mf < 4; mf++) {
        #pragma unroll
        for (int nf = 0; nf < 8; nf++) {
            float* v = acc[mf][nf];
            if (hd) {
                int gr0 = r0 + mf * 16, gr1 = gr0 + 8;
                int gc0 = c0 + nf * 8,  gc1 = gc0 + 1;
                if (gc0 == gr0) g_diag[gr0] = v[0] * INV_T;
                if (gc1 == gr0) g_diag[gr0] = v[1] * INV_T;
                if (gc0 == gr1) g_diag[gr1] = v[2] * INV_T;
                if (gc1 == gr1) g_diag[gr1] = v[3] * INV_T;
            }
            float e0 = exp2_fast((v[0] - 1.0f) * C1);
            float e1 = exp2_fast((v[1] - 1.0f) * C1);
            float e2 = exp2_fast((v[2] - 1.0f) * C1);
            float e3 = exp2_fast((v[3] - 1.0f) * C1);
            rs[mf][0] += e0 + e1;
            rs[mf][1] += e2 + e3;
            cs[nf][0] += e0 + e2;
            cs[nf][1] += e1 + e3;
        }
    }

    // row sums: reduce across lane&3 (cols within warp)
    #pragma unroll
    for (int mf = 0; mf < 4; mf++)
        #pragma unroll
        for (int h = 0; h < 2; h++) {
            float r = rs[mf][h];
            r += __shfl_xor_sync(0xffffffffu, r, 1);
            r += __shfl_xor_sync(0xffffffffu, r, 2);
            rs[mf][h] = r;
        }
    if ((lane & 3) == 0) {
        #pragma unroll
        for (int mf = 0; mf < 4; mf++)
            #pragma unroll
            for (int h = 0; h < 2; h++)
                rowp[nw * 128 + mw * 64 + mf * 16 + (lane >> 2) + 8 * h] = rs[mf][h];
    }

    // col sums: reduce across lane>>2 (rows within warp)
    #pragma unroll
    for (int nf = 0; nf < 8; nf++)
        #pragma unroll
        for (int e = 0; e < 2; e++) {
            float cv = cs[nf][e];
            cv += __shfl_xor_sync(0xffffffffu, cv, 4);
            cv += __shfl_xor_sync(0xffffffffu, cv, 8);
            cv += __shfl_xor_sync(0xffffffffu, cv, 16);
            cs[nf][e] = cv;
        }
    if (lane < 4) {
        #pragma unroll
        for (int nf = 0; nf < 8; nf++)
            #pragma unroll
            for (int e = 0; e < 2; e++)
                colp[mw * 256 + nw * 64 + nf * 8 + 2 * lane + e] = cs[nf][e];
    }
    __syncthreads();

    if (tid < TM)
        g_row_part[(size_t)bj * NR + bi * TM + tid] =
            (rowp[tid] + rowp[128 + tid]) + (rowp[256 + tid] + rowp[384 + tid]);
    {
        // all 256 threads: one column each
        g_col_part[(size_t)bi * NR + bj * TN + tid] = colp[tid] + colp[256 + tid];
    }
}

// ---------------- kernel 3: per-row lse combine ----------------
__global__ void reduce_rows_kernel() {
    int r = blockIdx.x * 256 + threadIdx.x;
    float rs = 0.f, cs = 0.f;
    #pragma unroll 8
    for (int j = 0; j < NBJ; j++) rs += g_row_part[(size_t)j * NR + r];
    #pragma unroll 8
    for (int i = 0; i < NBI; i++) cs += g_col_part[(size_t)i * NR + r];
    float c = 0.5f * (logf(rs) + logf(cs)) + INV_T - g_diag[r];

    #pragma unroll
    for (int o = 16; o; o >>= 1) c += __shfl_xor_sync(0xffffffffu, c, o);
    __shared__ float red[8];
    int w = threadIdx.x >> 5, l = threadIdx.x & 31;
    if (l == 0) red[w] = c;
    __syncthreads();
    if (threadIdx.x == 0) {
        float t = 0.f;
        #pragma unroll
        for (int i = 0; i < 8; i++) t += red[i];
        g_block_part[blockIdx.x] = t;
    }
}

// ---------------- kernel 4: final scalar ----------------
__global__ void final_kernel(float* __restrict__ out) {
    float v = g_block_part[threadIdx.x];
    #pragma unroll
    for (int o = 16; o; o >>= 1) v += __shfl_xor_sync(0xffffffffu, v, o);
    if (threadIdx.x == 0) out[0] = v * (1.0f / (float)NR);
}

// ---------------- launch ----------------
extern "C" void kernel_launch(void* const* d_in, const int* in_sizes, int n_in,
                              void* d_out, int out_size) {
    const float* q = (const float*)d_in[0];
    const float* k = (const float*)d_in[1];
    float* out = (float*)d_out;

    cudaFuncSetAttribute(gemm_tile_kernel,
                         cudaFuncAttributeMaxDynamicSharedMemorySize, SMEM_TOTAL);

    norm_kernel<<<dim3(NR, 2), 256>>>(q, k);
    gemm_tile_kernel<<<dim3(NBJ, NBI), 256, SMEM_TOTAL>>>();
    reduce_rows_kernel<<<NR / 256, 256>>>();
    final_kernel<<<1, 32>>>(out);
}